// round 4
// baseline (speedup 1.0000x reference)
#include <cuda_runtime.h>
#include <cuda_bf16.h>

// QuantumSubgenerator: 12-qubit RY / CNOT-ring / RY circuit + <Z_q> readout,
// reduced exactly (Heisenberg picture) to closed-form trig products:
//
//   alpha_q = latent[b][q] + w0[q];  c_q=cos(alpha_q), s_q=sin(alpha_q)
//   out[b][0]  = cos(th_0) * prod_{1..11} c_r  - sin(th_0)*s_0*s_1
//   out[b][q]  = cos(th_q) * prod_{0..q}  c_r  - sin(th_q)*s_q*s_{q+1}  (1<=q<=10)
//   out[b][11] = cos(th_11)* prod_{0..11} c_r  - sin(th_11)*s_0*s_1*s_11
//
// Round 4: branch-free front end. All lanes issue their loads at instruction 1
// (index clamped to stay in bounds, so no predication ahead of the LDGs),
// 64 CTAs x 256 threads (16 segments of 16 lanes each), store is the only
// guarded op. Critical path: LDG -> FADD -> 2x MUFU -> 4-step shfl scan ->
// broadcast -> FMA -> STG.

#define NQ 12
#define FULL 0xFFFFFFFFu

__global__ void __launch_bounds__(256)
QuantumSubgenerator_25314537242888_kernel(const float* __restrict__ latent,
                                          const float* __restrict__ weights,
                                          float* __restrict__ out, int B) {
    int seg = threadIdx.x >> 4;                  // 16 segments per block
    int q   = threadIdx.x & 15;                  // lane within segment
    int b   = blockIdx.x * 16 + seg;             // batch element
    int ql  = q < NQ - 1 ? q : NQ - 1;           // clamped qubit (in-bounds)
    int bl  = b < B ? b : B - 1;

    // Unconditional loads — issue immediately, no branch in front.
    float lat = latent[(size_t)bl * NQ + ql];
    float w0  = __ldg(&weights[ql]);
    float w1  = __ldg(&weights[NQ + ql]);

    float c, s, cw, sw;
    __sincosf(lat + w0, &s, &c);                 // MUFU fast path
    __sincosf(w1, &sw, &cw);

    // Segmented (width=16) inclusive prefix product of c over lanes 1..q:
    // cp_q = prod_{1..q} c_r   (lane 0 contributes 1).
    float cp = (q == 0) ? 1.0f : c;
    #pragma unroll
    for (int d = 1; d < 16; d <<= 1) {
        float v = __shfl_up_sync(FULL, cp, d, 16);
        if (q >= d) cp *= v;
    }

    // Segment broadcasts (independent -> pipelined, not serialized).
    float c0   = __shfl_sync(FULL, c,  0, 16);
    float s0   = __shfl_sync(FULL, s,  0, 16);
    float s1   = __shfl_sync(FULL, s,  1, 16);
    float ptot = __shfl_sync(FULL, cp, NQ - 1, 16);   // prod_{1..11} c_r
    float snx  = __shfl_down_sync(FULL, s, 1, 16);    // s_{q+1}

    float o;
    if (q == 0) {
        o = cw * ptot - sw * (s0 * s1);
    } else if (q >= NQ - 1) {
        o = cw * (c0 * ptot) - sw * (s0 * s1 * s);
    } else {
        o = cw * (c0 * cp) - sw * (s * snx);
    }

    if (q < NQ && b < B)
        out[(size_t)b * NQ + q] = o;
}

extern "C" void kernel_launch(void* const* d_in, const int* in_sizes, int n_in,
                              void* d_out, int out_size) {
    const float* latent  = (const float*)d_in[0];
    const float* weights = (const float*)d_in[1];
    int lat_sz = in_sizes[0];
    // Robust to input-order surprises: weights tensor has exactly 2*NQ elems.
    if (n_in >= 2 && in_sizes[0] == 2 * NQ) {
        latent  = (const float*)d_in[1];
        weights = (const float*)d_in[0];
        lat_sz  = in_sizes[1];
    }
    int B = lat_sz / NQ;                 // 1024
    int blocks = (B + 15) / 16;          // 16 elements per 256-thread block
    QuantumSubgenerator_25314537242888_kernel<<<blocks, 256>>>(
        latent, weights, (float*)d_out, B);
}